// round 17
// baseline (speedup 1.0000x reference)
#include <cuda_runtime.h>
#include <cuda_fp16.h>
#include <math.h>
#include <stdint.h>

#define NB   4
#define NS   2048
#define NH   16
#define NHD  128
#define NRD  64
#define NLAT 512
#define NHID 2048
#define NM   (NB*NS)

// ---------------- device scratch ----------------
__device__ float g_krr [(size_t)NM*NRD];
__device__ float g_cs  [NS*32];
__device__ float g_sn  [NS*32];

// fp16 operands
__device__ __half g_xs  [(size_t)NM*NHID];     // x fp16
__device__ __half g_wd  [(size_t)1152*2048];   // [wq_down|wkv_down|wk_rope|pad] T
__device__ __half g_wuq [(size_t)2048*512];    // [wq_up|wq_rope] T
__device__ __half g_wukv[(size_t)3072*512];    // [wk_up|wv_up] T
__device__ __half g_woh [(size_t)2048*2048];   // wo T
__device__ __half g_lat [(size_t)NM*1024];     // latents
__device__ __half g_qrh [(size_t)NM*1024];     // q_rope pre-rotation fp16
__device__ __half g_V   [(size_t)NM*NHID];     // V
__device__ __half g_Qs  [(size_t)NM*NHID];     // Q (head-interleaved, pre-scaled)
__device__ __half g_Ks  [(size_t)NM*NHID];     // K (head-interleaved)
__device__ __half g_ch  [(size_t)NM*NHID];     // ctx

// ---------------- PTX helpers ----------------
__device__ __forceinline__ void cp16(uint32_t s, const void* g) {
    asm volatile("cp.async.cg.shared.global [%0], [%1], 16;\n" :: "r"(s), "l"(g));
}

#define LDM_X4(R, addr) \
    asm volatile("ldmatrix.sync.aligned.m8n8.x4.shared.b16 {%0,%1,%2,%3}, [%4];" \
        : "=r"(R[0]), "=r"(R[1]), "=r"(R[2]), "=r"(R[3]) : "r"(addr))
#define LDM_X4_T(R, addr) \
    asm volatile("ldmatrix.sync.aligned.m8n8.x4.trans.shared.b16 {%0,%1,%2,%3}, [%4];" \
        : "=r"(R[0]), "=r"(R[1]), "=r"(R[2]), "=r"(R[3]) : "r"(addr))
#define MMAH16816(D, A, B0, B1) \
    asm volatile("mma.sync.aligned.m16n8k16.row.col.f32.f16.f16.f32 " \
        "{%0,%1,%2,%3}, {%4,%5,%6,%7}, {%8,%9}, {%0,%1,%2,%3};" \
        : "+f"(D[0]), "+f"(D[1]), "+f"(D[2]), "+f"(D[3]) \
        : "r"(A[0]), "r"(A[1]), "r"(A[2]), "r"(A[3]), "r"(B0), "r"(B1))

__device__ __forceinline__ uint32_t pack_f16(float a, float b) {   // lo=h(a), hi=h(b)
    uint32_t r;
    asm("cvt.rn.f16x2.f32 %0, %1, %2;" : "=r"(r) : "f"(b), "f"(a));
    return r;
}

#define QSCALE 0.08838834764831845f

// ---------------- x convert fp32 -> fp16 ----------------
__global__ void cvt4h_kernel(const float4* __restrict__ in, uint32_t* __restrict__ out)
{
    size_t i = (size_t)blockIdx.x * blockDim.x + threadIdx.x;
    float4 f = in[i];
    out[2*i]   = pack_f16(f.x, f.y);
    out[2*i+1] = pack_f16(f.z, f.w);
}

// batched transpose fp32 [K,N] -> fp16 [N,K], 8 weights in one launch
struct TAll {
    const float* src[8];
    __half* dst[8];
    int K[8];
    int N[8];
    int start[9];
};

__global__ void wtrans_all_kernel(TAll ta)
{
    __shared__ float t[32][33];
    int bid = blockIdx.x;
    int i = 0;
    #pragma unroll
    for (int j = 1; j < 8; j++) if (bid >= ta.start[j]) i = j;
    int lb = bid - ta.start[i];
    int K = ta.K[i], N = ta.N[i];
    int nbx = N >> 5;
    int n0 = (lb % nbx) * 32, k0 = (lb / nbx) * 32;
    const float* src = ta.src[i];
    __half* dst = ta.dst[i];

    int tx = threadIdx.x, ty = threadIdx.y;
    #pragma unroll
    for (int j = 0; j < 4; j++)
        t[ty + j*8][tx] = src[(size_t)(k0 + ty + j*8) * N + n0 + tx];
    __syncthreads();
    #pragma unroll
    for (int j = 0; j < 4; j++)
        dst[(size_t)(n0 + ty + j*8) * K + k0 + tx] = __float2half_rn(t[tx][ty + j*8]);
}

// ---------------- single-fp16 GEMM, CTA tile 128x64 ----------------
// C[M,N] = A[M,K(lda)] @ Bt[N,K]^T. BK=32, 128 thr (4 warps 2x2), warp tile 64x32.
// EPI 1: fp32 + bias (Nc).
// EPI 4: fp16 Ch (Ns) cols<boundary; fp32 C at cs<Nc >= boundary, else discard. (down+krr)
// EPI 5: cols<boundary: qc -> Ch head-remap (stride 2048, +scale); cols>=: fp16 Ch2 (1024). (up-q)
// EPI 6: cols<boundary: kc -> Ch head-remap (stride 2048); cols>=: fp16 Ch2 (Ns). (up-kv)
#define SA_ELEMS (128*40)
#define SB_ELEMS (64*40)
#define HG_SMEM ((2*(SA_ELEMS + SB_ELEMS))*2)   // 30720 B

__device__ __forceinline__ void hgemm_fill(
    uint32_t sb, int buf,
    const __half* __restrict__ A, const __half* __restrict__ B,
    int tid, int row0, int col0, int k0, int lda, int ldb)
{
    uint32_t abase = sb + (uint32_t)buf * (SA_ELEMS + SB_ELEMS) * 2;
    // A: 128 rows x 4 chunks = 512
    #pragma unroll
    for (int j = 0; j < 4; j++) {
        int chunk = tid + 128*j;
        int r = chunk >> 2, cc = chunk & 3;
        size_t ga = (size_t)(row0 + r) * lda + k0 + cc*8;
        cp16(abase + (uint32_t)(r*40 + cc*8)*2, A + ga);
    }
    // B: 64 rows x 4 chunks = 256
    #pragma unroll
    for (int j = 0; j < 2; j++) {
        int chunk = tid + 128*j;
        int r = chunk >> 2, cc = chunk & 3;
        size_t gb = (size_t)(col0 + r) * ldb + k0 + cc*8;
        cp16(abase + SA_ELEMS*2 + (uint32_t)(r*40 + cc*8)*2, B + gb);
    }
    asm volatile("cp.async.commit_group;");
}

template<int EPI>
__global__ void __launch_bounds__(128)
hgemm_kernel(const __half* __restrict__ A, const __half* __restrict__ B,
             float* __restrict__ C, __half* __restrict__ Ch, __half* __restrict__ Ch2,
             const float* __restrict__ bias,
             int lda, int K, int Nc, int Ns, int boundary)
{
    extern __shared__ __half hsm[];
    const uint32_t sb = (uint32_t)__cvta_generic_to_shared(hsm);

    const int tid  = threadIdx.x;
    const int lane = tid & 31;
    const int wid  = tid >> 5;
    const int m0w  = (wid >> 1) * 64;
    const int n0w  = (wid & 1) * 32;
    const int row0 = blockIdx.y * 128;
    const int col0 = blockIdx.x * 64;

    float acc[4][4][4];
    #pragma unroll
    for (int i = 0; i < 4; i++)
        #pragma unroll
        for (int j = 0; j < 4; j++)
            #pragma unroll
            for (int k = 0; k < 4; k++) acc[i][j][k] = 0.f;

    const int niter = K >> 5;
    hgemm_fill(sb, 0, A, B, tid, row0, col0, 0, lda, K);

    const int aRow  = m0w + (lane & 15);
    const int aCol8 = 8 * (lane >> 4);
    const int bRow  = n0w + (lane & 15);

    for (int it = 0; it < niter; ++it) {
        const int buf = it & 1;
        if (it + 1 < niter) {
            hgemm_fill(sb, buf ^ 1, A, B, tid, row0, col0, (it+1)*32, lda, K);
            asm volatile("cp.async.wait_group 1;");
        } else {
            asm volatile("cp.async.wait_group 0;");
        }
        __syncthreads();

        uint32_t abase = sb + (uint32_t)buf * (SA_ELEMS + SB_ELEMS) * 2;
        #pragma unroll
        for (int sub = 0; sub < 32; sub += 16) {
            uint32_t ah[4][4];
            #pragma unroll
            for (int mt = 0; mt < 4; mt++) {
                LDM_X4(ah[mt], abase + (uint32_t)((aRow + mt*16)*40 + sub + aCol8)*2);
            }
            // B non-trans ldmatrix on K-major: pairs n0-7 -> (r0,r2); n8-15 -> (r1,r3)
            #pragma unroll
            for (int ng = 0; ng < 2; ng++) {
                uint32_t bb[4];
                LDM_X4(bb, abase + SA_ELEMS*2 +
                    (uint32_t)((bRow + ng*16)*40 + sub + aCol8)*2);
                #pragma unroll
                for (int half = 0; half < 2; half++) {
                    uint32_t b0 = bb[half], b1 = bb[half+2];
                    int nt = ng*2 + half;
                    #pragma unroll
                    for (int mt = 0; mt < 4; mt++)
                        MMAH16816(acc[mt][nt], ah[mt], b0, b1);
                }
            }
        }
        __syncthreads();
    }

    #pragma unroll
    for (int mt = 0; mt < 4; mt++) {
        #pragma unroll
        for (int nt = 0; nt < 4; nt++) {
            int r  = row0 + m0w + mt*16 + (lane >> 2);
            int cc = col0 + n0w + nt*8 + (lane & 3)*2;
            float a0 = acc[mt][nt][0], a1 = acc[mt][nt][1];
            float a2 = acc[mt][nt][2], a3 = acc[mt][nt][3];
            if (EPI == 1) {
                float b0 = bias[cc], b1 = bias[cc+1];
                *(float2*)(C + (size_t)r     * Nc + cc) = make_float2(a0 + b0, a1 + b1);
                *(float2*)(C + (size_t)(r+8) * Nc + cc) = make_float2(a2 + b0, a3 + b1);
            } else if (EPI == 4) {
                if (cc < boundary) {
                    *(uint32_t*)(Ch + (size_t)r     * Ns + cc) = pack_f16(a0, a1);
                    *(uint32_t*)(Ch + (size_t)(r+8) * Ns + cc) = pack_f16(a2, a3);
                } else {
                    int cs = cc - boundary;
                    if (cs < Nc) {
                        *(float2*)(C + (size_t)r     * Nc + cs) = make_float2(a0, a1);
                        *(float2*)(C + (size_t)(r+8) * Nc + cs) = make_float2(a2, a3);
                    }
                }
            } else if (EPI == 5) {
                if (cc < boundary) {
                    int h = cc >> 6, d = cc & 63;
                    size_t o = (size_t)h*128 + d;
                    *(uint32_t*)(Ch + (size_t)r     * 2048 + o) = pack_f16(a0*QSCALE, a1*QSCALE);
                    *(uint32_t*)(Ch + (size_t)(r+8) * 2048 + o) = pack_f16(a2*QSCALE, a3*QSCALE);
                } else {
                    int cq = cc - boundary;
                    *(uint32_t*)(Ch2 + (size_t)r     * 1024 + cq) = pack_f16(a0, a1);
                    *(uint32_t*)(Ch2 + (size_t)(r+8) * 1024 + cq) = pack_f16(a2, a3);
                }
            } else {   // EPI == 6
                if (cc < boundary) {
                    int h = cc >> 6, d = cc & 63;
                    size_t o = (size_t)h*128 + d;
                    *(uint32_t*)(Ch + (size_t)r     * 2048 + o) = pack_f16(a0, a1);
                    *(uint32_t*)(Ch + (size_t)(r+8) * 2048 + o) = pack_f16(a2, a3);
                } else {
                    int cs = cc - boundary;
                    *(uint32_t*)(Ch2 + (size_t)r     * Ns + cs) = pack_f16(a0, a1);
                    *(uint32_t*)(Ch2 + (size_t)(r+8) * Ns + cs) = pack_f16(a2, a3);
                }
            }
        }
    }
}

// ---------------- RoPE LUT + rope-only pack ----------------
__global__ void rope_lut_kernel()
{
    int idx = blockIdx.x * blockDim.x + threadIdx.x;
    int pos = idx >> 5, fi = idx & 31;
    float inv = powf(10000.f, -(float)(2*fi) / 64.f);
    float ang = (float)pos * inv;
    float s, c;
    sincosf(ang, &s, &c);
    g_cs[idx] = c;
    g_sn[idx] = s;
}

__global__ void pack_rope_kernel()
{
    int gidx = blockIdx.x * blockDim.x + threadIdx.x;
    const int TOT = NM * 1024;
    bool isK = gidx >= TOT;
    int idx = isK ? (gidx - TOT) : gidx;
    int row = idx >> 10;
    int c   = idx & 1023;
    int h = c >> 6, dd = c & 63;
    int pos = row & (NS - 1);
    float cs = g_cs[pos*32 + (dd & 31)], sn = g_sn[pos*32 + (dd & 31)];
    if (!isK) {
        const __half* qr = g_qrh + (size_t)row*1024 + h*64;
        float v = __half2float(qr[dd]);
        float w = (dd < 32) ? -__half2float(qr[dd + 32]) : __half2float(qr[dd - 32]);
        float out = (v * cs + w * sn) * QSCALE;
        g_Qs[(size_t)row*2048 + h*128 + 64 + dd] = __float2half_rn(out);
    } else {
        const float* kr = g_krr + (size_t)row*NRD;
        float v = kr[dd];
        float w = (dd < 32) ? -kr[dd + 32] : kr[dd - 32];
        float out = v * cs + w * sn;
        g_Ks[(size_t)row*2048 + h*128 + 64 + dd] = __float2half_rn(out);
    }
}

// ---------------- flash attention: all-single-fp16, heavy-tiles-first ----------------
#define FS 136
#define FTILE_B (64*FS*2)
#define FL_SMEM (3*FTILE_B)

__global__ void __launch_bounds__(128)
flasht_kernel(const __half* __restrict__ Q, const __half* __restrict__ K,
              const __half* __restrict__ V, __half* __restrict__ O)
{
    extern __shared__ __half fsm[];
    const uint32_t sb = (uint32_t)__cvta_generic_to_shared(fsm);

    const int tid = threadIdx.x;
    const int lane = tid & 31;
    const int w = tid >> 5;
    const int lr = lane >> 2;
    const int lc = (lane & 3) * 2;
    const int h = blockIdx.y, b = blockIdx.z;
    // reverse mapping: heaviest q-tiles (most KV tiles) scheduled first
    const int qt = (int)gridDim.x - 1 - (int)blockIdx.x;
    const int q0 = qt * 64;
    const size_t base = ((size_t)b * NS) * NHID + (size_t)h * NHD;

    for (int i = tid; i < 1024; i += 128) {
        int r = i >> 4, c = (i & 15) << 3;
        uint32_t so = (uint32_t)(r*FS + c) * 2;
        cp16(sb + so, Q + base + (size_t)(q0 + r) * NHID + c);
    }
    asm volatile("cp.async.commit_group;");

    float m0 = -1e30f, m1 = -1e30f, l0 = 0.f, l1 = 0.f;
    float o[16][4];
    #pragma unroll
    for (int i = 0; i < 16; i++)
        #pragma unroll
        for (int j = 0; j < 4; j++) o[i][j] = 0.f;

    const int aRow = w*16 + (lane & 15);
    const int hi8  = 8 * (lane >> 4);
    const int ntiles = qt + 1;

    for (int t = 0; t < ntiles; t++) {
        const int k0 = t * 64;
        if (t) __syncthreads();
        for (int i = tid; i < 1024; i += 128) {
            int r = i >> 4, c = (i & 15) << 3;
            uint32_t so = (uint32_t)(r*FS + c) * 2;
            size_t go = base + (size_t)(k0 + r) * NHID + c;
            cp16(sb + 1*FTILE_B + so, K + go);
            cp16(sb + 2*FTILE_B + so, V + go);
        }
        asm volatile("cp.async.commit_group;");
        asm volatile("cp.async.wait_group 0;");
        __syncthreads();

        float s[8][4];
        #pragma unroll
        for (int i = 0; i < 8; i++)
            #pragma unroll
            for (int j = 0; j < 4; j++) s[i][j] = 0.f;

        #pragma unroll
        for (int kc = 0; kc < 8; kc++) {
            uint32_t qs[4];
            LDM_X4(qs, sb + (uint32_t)(aRow*FS + kc*16 + hi8)*2);
            #pragma unroll
            for (int g = 0; g < 4; g++) {
                uint32_t ks[4];
                LDM_X4(ks, sb + 1*FTILE_B + (uint32_t)((g*16 + (lane & 15))*FS + kc*16 + hi8)*2);
                MMAH16816(s[2*g],   qs, ks[0], ks[2]);
                MMAH16816(s[2*g+1], qs, ks[1], ks[3]);
            }
        }

        if (t == qt) {
            int r0 = q0 + w*16 + lr, r1 = r0 + 8;
            #pragma unroll
            for (int nt = 0; nt < 8; nt++) {
                int c = k0 + nt*8 + lc;
                if (c     > r0) s[nt][0] = -1e30f;
                if (c + 1 > r0) s[nt][1] = -1e30f;
                if (c     > r1) s[nt][2] = -1e30f;
                if (c + 1 > r1) s[nt][3] = -1e30f;
            }
        }

        float mt0 = -1e30f, mt1 = -1e30f;
        #pragma unroll
        for (int nt = 0; nt < 8; nt++) {
            mt0 = fmaxf(mt0, fmaxf(s[nt][0], s[nt][1]));
            mt1 = fmaxf(mt1, fmaxf(s[nt][2], s[nt][3]));
        }
        mt0 = fmaxf(mt0, __shfl_xor_sync(0xffffffffu, mt0, 1));
        mt0 = fmaxf(mt0, __shfl_xor_sync(0xffffffffu, mt0, 2));
        mt1 = fmaxf(mt1, __shfl_xor_sync(0xffffffffu, mt1, 1));
        mt1 = fmaxf(mt1, __shfl_xor_sync(0xffffffffu, mt1, 2));
        float n0 = fmaxf(m0, mt0), n1 = fmaxf(m1, mt1);
        float corr0 = __expf(m0 - n0), corr1 = __expf(m1 - n1);
        m0 = n0; m1 = n1;

        float ps0 = 0.f, ps1 = 0.f;
        #pragma unroll
        for (int nt = 0; nt < 8; nt++) {
            s[nt][0] = __expf(s[nt][0] - n0);
            s[nt][1] = __expf(s[nt][1] - n0);
            s[nt][2] = __expf(s[nt][2] - n1);
            s[nt][3] = __expf(s[nt][3] - n1);
            ps0 += s[nt][0] + s[nt][1];
            ps1 += s[nt][2] + s[nt][3];
        }
        l0 = l0 * corr0 + ps0;
        l1 = l1 * corr1 + ps1;
        #pragma unroll
        for (int i = 0; i < 16; i++) {
            o[i][0] *= corr0; o[i][1] *= corr0;
            o[i][2] *= corr1; o[i][3] *= corr1;
        }

        #pragma unroll
        for (int kc = 0; kc < 4; kc++) {
            uint32_t ph[4];
            ph[0] = pack_f16(s[2*kc][0],   s[2*kc][1]);
            ph[1] = pack_f16(s[2*kc][2],   s[2*kc][3]);
            ph[2] = pack_f16(s[2*kc+1][0], s[2*kc+1][1]);
            ph[3] = pack_f16(s[2*kc+1][2], s[2*kc+1][3]);
            #pragma unroll
            for (int np = 0; np < 8; np++) {
                uint32_t vv[4];
                LDM_X4_T(vv, sb + 2*FTILE_B +
                    (uint32_t)((kc*16 + (lane & 15))*FS + np*16 + hi8)*2);
                MMAH16816(o[2*np],   ph, vv[0], vv[1]);
                MMAH16816(o[2*np+1], ph, vv[2], vv[3]);
            }
        }
    }

    float t0 = l0, t1 = l1;
    t0 += __shfl_xor_sync(0xffffffffu, t0, 1);
    t0 += __shfl_xor_sync(0xffffffffu, t0, 2);
    t1 += __shfl_xor_sync(0xffffffffu, t1, 1);
    t1 += __shfl_xor_sync(0xffffffffu, t1, 2);
    float inv0 = 1.f / t0, inv1 = 1.f / t1;
    int r0 = q0 + w*16 + lr;
    #pragma unroll
    for (int nt = 0; nt < 16; nt++) {
        int c = nt*8 + lc;
        size_t off0 = base + (size_t)r0 * NHID + c;
        size_t off1 = base + (size_t)(r0+8) * NHID + c;
        *(uint32_t*)(O + off0) = pack_f16(o[nt][0]*inv0, o[nt][1]*inv0);
        *(uint32_t*)(O + off1) = pack_f16(o[nt][2]*inv1, o[nt][3]*inv1);
    }
}

// ---------------- host launcher ----------------
extern "C" void kernel_launch(void* const* d_in, const int* in_sizes, int n_in,
                              void* d_out, int out_size)
{
    const float* x        = (const float*)d_in[0];
    const float* wq_down  = (const float*)d_in[1];
    const float* wq_up    = (const float*)d_in[2];
    const float* wq_rope  = (const float*)d_in[3];
    const float* wk_rope  = (const float*)d_in[4];
    const float* wkv_down = (const float*)d_in[5];
    const float* wk_up    = (const float*)d_in[6];
    const float* wv_up    = (const float*)d_in[7];
    const float* wo       = (const float*)d_in[8];
    const float* bo       = (const float*)d_in[9];
    float* out = (float*)d_out;

    float *krr;
    cudaGetSymbolAddress((void**)&krr, g_krr);

    __half *xs, *wd, *wuq, *wukv, *woh, *lat, *qrh, *V, *Qs, *Ks, *ch;
    cudaGetSymbolAddress((void**)&xs,   g_xs);
    cudaGetSymbolAddress((void**)&wd,   g_wd);
    cudaGetSymbolAddress((void**)&wuq,  g_wuq);
    cudaGetSymbolAddress((void**)&wukv, g_wukv);
    cudaGetSymbolAddress((void**)&woh,  g_woh);
    cudaGetSymbolAddress((void**)&lat,  g_lat);
    cudaGetSymbolAddress((void**)&qrh,  g_qrh);
    cudaGetSymbolAddress((void**)&V,    g_V);
    cudaGetSymbolAddress((void**)&Qs,   g_Qs);
    cudaGetSymbolAddress((void**)&Ks,   g_Ks);
    cudaGetSymbolAddress((void**)&ch,   g_ch);

    const size_t XN = (size_t)NM*NHID;

    cudaFuncSetAttribute(hgemm_kernel<1>, cudaFuncAttributeMaxDynamicSharedMemorySize, HG_SMEM);
    cudaFuncSetAttribute(hgemm_kernel<4>, cudaFuncAttributeMaxDynamicSharedMemorySize, HG_SMEM);
    cudaFuncSetAttribute(hgemm_kernel<5>, cudaFuncAttributeMaxDynamicSharedMemorySize, HG_SMEM);
    cudaFuncSetAttribute(hgemm_kernel<6>, cudaFuncAttributeMaxDynamicSharedMemorySize, HG_SMEM);
    cudaFuncSetAttribute(flasht_kernel,   cudaFuncAttributeMaxDynamicSharedMemorySize, FL_SMEM);

    dim3 thr(256);
    dim3 gthr(128);

    // (1) RoPE LUT
    rope_lut_kernel<<<256, 256>>>();

    // (2) x -> fp16
    cvt4h_kernel<<<(unsigned)(XN/1024), 256>>>((const float4*)x, (uint32_t*)xs);

    // (3) batched weight transpose -> fp16 (8 weights)
    {
        TAll ta;
        const float* srcs[8] = { wq_down, wkv_down, wk_rope, wq_up, wq_rope, wk_up, wv_up, wo };
        __half* dsts[8] = { wd,            wd + (size_t)512*2048,  wd + (size_t)1024*2048,
                            wuq,           wuq + (size_t)1024*512,
                            wukv,          wukv + (size_t)1024*512,
                            woh };
        int Ks_[8] = { 2048, 2048, 2048, 512, 512, 512, 512, 2048 };
        int Ns_[8] = { 512, 512, 64, 1024, 1024, 1024, 2048, 2048 };
        int total = 0;
        for (int i = 0; i < 8; i++) {
            ta.src[i] = srcs[i]; ta.dst[i] = dsts[i];
            ta.K[i] = Ks_[i]; ta.N[i] = Ns_[i];
            ta.start[i] = total;
            total += (Ns_[i]/32) * (Ks_[i]/32);
        }
        ta.start[8] = total;
        wtrans_all_kernel<<<total, dim3(32, 8)>>>(ta);
    }

    // (4) fused down projection + wk_rope: N=1152 (EPI=4)
    hgemm_kernel<4><<<dim3(18, 64), gthr, HG_SMEM>>>(
        xs, wd, krr, lat, nullptr, nullptr,
        2048, 2048, 64, 1024, 1024);

    // (5) fused up-q (EPI=5): qc -> Qs head-remapped+scaled; qr -> qrh temp
    hgemm_kernel<5><<<dim3(32, 64), gthr, HG_SMEM>>>(
        lat, wuq, nullptr, Qs, qrh, nullptr,
        1024, 512, 0, 0, 1024);

    // (6) fused up-kv (EPI=6): kc -> Ks head-remapped; V direct
    hgemm_kernel<6><<<dim3(48, 64), gthr, HG_SMEM>>>(
        lat + 512, wukv, nullptr, Ks, V, nullptr,
        1024, 512, 0, 2048, 1024);

    // (7) rope-only pack: Q rope (from qrh) + K rope (from krr, broadcast)
    pack_rope_kernel<<<(2*NM*1024)/256, thr>>>();

    // (8) flash attention (all fp16, heavy-first) -> ctx fp16
    flasht_kernel<<<dim3(NS/64, NH, NB), 128, FL_SMEM>>>(Qs, Ks, V, ch);

    // (9) fp16 output projection + bias (EPI=1)
    hgemm_kernel<1><<<dim3(32, 64), gthr, HG_SMEM>>>(
        ch, woh, out, nullptr, nullptr, bo,
        2048, 2048, 2048, 0, 0);
}